// round 10
// baseline (speedup 1.0000x reference)
#include <cuda_runtime.h>
#include <cuda_bf16.h>
#include <cstdint>

// Problem constants
#define BATCH 8
#define DIM   512
#define SEQ   8192
#define HALF  256   // DIM/2 channels per direction output

// Scratch: hg[dir][b][channel(512)][l]  (fore conv output, back conv output)
// 2*8*512*8192 floats = 268 MB, static device allocation (allowed; zero-init BSS).
__device__ float g_hg[2ULL * BATCH * DIM * SEQ];

// ---------------------------------------------------------------------------
// GEMM: hg[dir][b][e][l] = sum_d W_dir[e][d] * x[b][d][l] + bias_dir[e]
// M = 1024 (512 fore rows + 512 back rows), N = 8192, K = 512, batched over B.
// Classic SIMT fp32: 128x128 tile, BK=8, 256 threads, 8x8 per thread.
// ---------------------------------------------------------------------------
__global__ __launch_bounds__(256, 2)
void gemm_kernel(const float* __restrict__ x,
                 const float* __restrict__ w_fore, const float* __restrict__ b_fore,
                 const float* __restrict__ w_back, const float* __restrict__ b_back)
{
    const int mt = blockIdx.x;          // 0..7   (M tiles, 128 rows each)
    const int nt = blockIdx.y;          // 0..63  (N tiles)
    const int b  = blockIdx.z;          // batch
    const int m0 = mt * 128;
    const int n0 = nt * 128;

    const int dir = (m0 >= DIM) ? 1 : 0;
    const int e0  = m0 & (DIM - 1);     // channel base within this direction
    const float* __restrict__ W    = dir ? (w_back + (size_t)e0 * DIM) : (w_fore + (size_t)e0 * DIM);
    const float* __restrict__ bias = dir ? (b_back + e0) : (b_fore + e0);

    const float* __restrict__ X = x + ((size_t)b * DIM) * SEQ + n0;
    float* __restrict__ C = g_hg + (((size_t)dir * BATCH + b) * DIM + e0) * SEQ + n0;

    __shared__ float As[8][132];   // [k][m], padded: conflict-free column reads
    __shared__ float Bs[8][128];   // [k][n]

    float acc[8][8];
#pragma unroll
    for (int i = 0; i < 8; i++)
#pragma unroll
        for (int j = 0; j < 8; j++) acc[i][j] = 0.f;

    const int tid = threadIdx.x;
    const int r0 = (tid >> 4) * 8;
    const int c0 = (tid & 15) * 8;

    for (int kk0 = 0; kk0 < DIM; kk0 += 8) {
        // Load A tile (128 rows x 8 k): idx -> m = idx>>3, k = idx&7
#pragma unroll
        for (int j = 0; j < 4; j++) {
            int idx = tid + 256 * j;
            int k = idx & 7, m = idx >> 3;
            As[k][m] = W[(size_t)m * DIM + kk0 + k];
        }
        // Load B tile (8 k x 128 n): coalesced along n
#pragma unroll
        for (int j = 0; j < 4; j++) {
            int idx = tid + 256 * j;
            int kb = idx >> 7, n = idx & 127;
            Bs[kb][n] = X[(size_t)(kk0 + kb) * SEQ + n];
        }
        __syncthreads();

#pragma unroll
        for (int kk = 0; kk < 8; kk++) {
            float a[8], bb[8];
#pragma unroll
            for (int j = 0; j < 8; j++) a[j] = As[kk][r0 + j];
#pragma unroll
            for (int j = 0; j < 8; j++) bb[j] = Bs[kk][c0 + j];
#pragma unroll
            for (int i = 0; i < 8; i++)
#pragma unroll
                for (int j = 0; j < 8; j++) acc[i][j] = fmaf(a[i], bb[j], acc[i][j]);
        }
        __syncthreads();
    }

    // Epilogue: add bias, vectorized store
#pragma unroll
    for (int i = 0; i < 8; i++) {
        float bi = bias[r0 + i];
        float* row = C + (size_t)(r0 + i) * SEQ + c0;
        float4 v0 = make_float4(acc[i][0] + bi, acc[i][1] + bi, acc[i][2] + bi, acc[i][3] + bi);
        float4 v1 = make_float4(acc[i][4] + bi, acc[i][5] + bi, acc[i][6] + bi, acc[i][7] + bi);
        *reinterpret_cast<float4*>(row)     = v0;
        *reinterpret_cast<float4*>(row + 4) = v1;
    }
}

// ---------------------------------------------------------------------------
// minGRU scan. h_t = a_t * h_{t-1} + b_t, h_0 = 0, with
//   a_t = sigmoid(-gate_t), b_t = sigmoid(gate_t) * g(h_t_in),
//   g(x) = (x >= 0) ? 1 + x : exp(x)
// (Exact linear-space equivalent of the reference's log-space
//  cumsum + cumlogsumexp; all terms positive so fp32 is stable.)
// One CTA per (dir, b, channel): 4096 CTAs, 256 threads x 32 elems.
// dir==1 scans the sequence in reverse (back direction).
// Smem index skew p + (p>>5): per-thread stride-32 segment access becomes
// bank-conflict-free ((tid + j) % 32).
// ---------------------------------------------------------------------------
#define IDX(p) ((p) + ((p) >> 5))
#define SCAN_SMEM_ELEMS (SEQ + (SEQ >> 5))   // 8448 per array

__global__ __launch_bounds__(256, 3)
void scan_kernel(const float* __restrict__ hg, float* __restrict__ out)
{
    extern __shared__ float smem[];
    float* sa = smem;                       // a_t
    float* sb = smem + SCAN_SMEM_ELEMS;     // b_t, overwritten with h_t

    __shared__ float wA[256];
    __shared__ float wB[256];

    const int id  = blockIdx.x;             // 0..4095
    const int dir = id >> 11;
    const int rem = id & 2047;
    const int b   = rem >> 8;
    const int ch  = rem & 255;

    const float* __restrict__ hrow = hg + (((size_t)dir * BATCH + b) * DIM + ch) * SEQ;
    const float* __restrict__ grow = hrow + (size_t)HALF * SEQ;   // gate channel ch+256

    const int tid = threadIdx.x;

    // Load + elementwise transform (reverse the sequence into smem for dir==1)
    for (int t = tid; t < SEQ; t += 256) {
        float h = hrow[t];
        float g = grow[t];
        float s = 1.f / (1.f + __expf(-g));   // sigmoid(gate)
        float a = 1.f / (1.f + __expf(g));    // sigmoid(-gate)
        float gh = (h >= 0.f) ? (1.f + h) : __expf(h);
        int p = dir ? (SEQ - 1 - t) : t;
        sa[IDX(p)] = a;
        sb[IDX(p)] = s * gh;
    }
    __syncthreads();

    // Local affine composition over this thread's 32-element segment:
    // (A, B): h_out = A * h_in + B.  Append (a,b): A <- a*A, B <- a*B + b.
    const int base = tid * 32;
    float A = 1.f, Bc = 0.f;
#pragma unroll
    for (int j = 0; j < 32; j++) {
        float at = sa[IDX(base + j)];
        float bt = sb[IDX(base + j)];
        A  = at * A;
        Bc = fmaf(at, Bc, bt);
    }
    wA[tid] = A;
    wB[tid] = Bc;
    __syncthreads();

    // Hillis-Steele inclusive scan over 256 (A,B) pairs.
    float ca = A, cb = Bc;
    for (int off = 1; off < 256; off <<= 1) {
        float pa = 1.f, pb = 0.f;
        if (tid >= off) { pa = wA[tid - off]; pb = wB[tid - off]; }
        __syncthreads();
        float na = ca * pa;
        float nb = fmaf(ca, pb, cb);
        ca = na; cb = nb;
        wA[tid] = ca;
        wB[tid] = cb;
        __syncthreads();
    }

    // h at segment start = inclusive B of previous thread (h_0 = 0).
    float h = (tid == 0) ? 0.f : wB[tid - 1];

    // Replay segment, overwrite sb with h_t.
#pragma unroll
    for (int j = 0; j < 32; j++) {
        float at = sa[IDX(base + j)];
        h = fmaf(at, h, sb[IDX(base + j)]);
        sb[IDX(base + j)] = h;
    }
    __syncthreads();

    // Coalesced write-out. out[b][dir*256 + ch][l]; back maps scan pos t -> l = SEQ-1-t.
    float* __restrict__ orow = out + (((size_t)b * DIM) + dir * HALF + ch) * SEQ;
    for (int t = tid; t < SEQ; t += 256) {
        int l = dir ? (SEQ - 1 - t) : t;
        orow[l] = sb[IDX(t)];
    }
}

// ---------------------------------------------------------------------------
// Launch — stateless and deterministic (no static guards; attribute call is
// idempotent and made unconditionally on every invocation).
// ---------------------------------------------------------------------------
extern "C" void kernel_launch(void* const* d_in, const int* in_sizes, int n_in,
                              void* d_out, int out_size)
{
    const float* x      = (const float*)d_in[0];
    const float* w_fore = (const float*)d_in[1];
    const float* b_fore = (const float*)d_in[2];
    const float* w_back = (const float*)d_in[3];
    const float* b_back = (const float*)d_in[4];
    float* out = (float*)d_out;

    float* hg = nullptr;
    cudaGetSymbolAddress((void**)&hg, g_hg);

    // GEMM: grid.x = M tiles so consecutive CTAs share the same X tile in L2.
    dim3 ggrid(1024 / 128, SEQ / 128, BATCH);
    gemm_kernel<<<ggrid, 256>>>(x, w_fore, b_fore, w_back, b_back);

    // Scan: needs > 48 KB dynamic smem; set attribute every call (no static state).
    const size_t smem_bytes = 2 * SCAN_SMEM_ELEMS * sizeof(float);   // 67584
    cudaFuncSetAttribute(scan_kernel, cudaFuncAttributeMaxDynamicSharedMemorySize,
                         (int)smem_bytes);
    scan_kernel<<<2 * BATCH * HALF, 256, smem_bytes>>>(hg, out);
}

// round 15
// speedup vs baseline: 3.2118x; 3.2118x over previous
#include <cuda_runtime.h>
#include <cuda_bf16.h>
#include <cstdint>

// Problem constants
#define BATCH 8
#define DIM   512
#define SEQ   8192
#define HALF  256

// ---------------------------------------------------------------------------
// Static device scratch
// ---------------------------------------------------------------------------
__device__ float         g_hg   [2ULL * BATCH * DIM * SEQ];     // 268 MB fp32
__device__ __nv_bfloat16 g_xt_hi[(size_t)BATCH * SEQ * DIM];    // [b][l][d]
__device__ __nv_bfloat16 g_xt_lo[(size_t)BATCH * SEQ * DIM];
__device__ __nv_bfloat16 g_w_hi [2 * DIM * DIM];                // [dir*512+e][d]
__device__ __nv_bfloat16 g_w_lo [2 * DIM * DIM];

// ---------------------------------------------------------------------------
// Helpers (all PTX here is plain sm_80-era — compiles at compute_103)
// ---------------------------------------------------------------------------
__device__ __forceinline__ uint32_t smem_u32(const void* p) {
    uint32_t a;
    asm("{ .reg .u64 t; cvta.to.shared.u64 t, %1; cvt.u32.u64 %0, t; }" : "=r"(a) : "l"(p));
    return a;
}
__device__ __forceinline__ void cpasync16(uint32_t dst, const void* src) {
    asm volatile("cp.async.cg.shared.global [%0], [%1], 16;" :: "r"(dst), "l"(src) : "memory");
}
#define CP_COMMIT() asm volatile("cp.async.commit_group;" ::: "memory")

#define LDSM_X4(r0, r1, r2, r3, addr) \
    asm volatile("ldmatrix.sync.aligned.m8n8.x4.shared.b16 {%0,%1,%2,%3}, [%4];" \
                 : "=r"(r0), "=r"(r1), "=r"(r2), "=r"(r3) : "r"(addr))

#define MMA16816(d, a, b0, b1) \
    asm volatile("mma.sync.aligned.m16n8k16.row.col.f32.bf16.bf16.f32 " \
                 "{%0,%1,%2,%3},{%4,%5,%6,%7},{%8,%9},{%0,%1,%2,%3};" \
                 : "+f"((d)[0]), "+f"((d)[1]), "+f"((d)[2]), "+f"((d)[3]) \
                 : "r"((a)[0]), "r"((a)[1]), "r"((a)[2]), "r"((a)[3]), "r"(b0), "r"(b1))

// ---------------------------------------------------------------------------
// Prepass 1: W (both dirs) -> bf16 hi/lo, layout [dir*512+e][d]
// ---------------------------------------------------------------------------
__global__ void wconv_kernel(const float* __restrict__ w_fore, const float* __restrict__ w_back)
{
    int idx = blockIdx.x * 256 + threadIdx.x;
    int row = idx >> 9;
    int col = idx & 511;
    float v = (row < DIM) ? w_fore[(size_t)row * DIM + col]
                          : w_back[(size_t)(row - DIM) * DIM + col];
    __nv_bfloat16 hi = __float2bfloat16(v);
    float r = v - __bfloat162float(hi);
    g_w_hi[idx] = hi;
    g_w_lo[idx] = __float2bfloat16(r);
}

// ---------------------------------------------------------------------------
// Prepass 2: X [b][d][l] fp32 -> Xt [b][l][d] bf16 hi/lo (32x32 transpose)
// ---------------------------------------------------------------------------
__global__ __launch_bounds__(256)
void xconv_kernel(const float* __restrict__ x)
{
    __shared__ float tile[32][33];
    const int l0 = blockIdx.x * 32;
    const int d0 = blockIdx.y * 32;
    const int b  = blockIdx.z;
    const int tx = threadIdx.x & 31;
    const int ty = threadIdx.x >> 5;

#pragma unroll
    for (int j = 0; j < 4; j++)
        tile[ty + 8 * j][tx] = x[((size_t)b * DIM + (d0 + ty + 8 * j)) * SEQ + l0 + tx];
    __syncthreads();
#pragma unroll
    for (int j = 0; j < 4; j++) {
        float v = tile[tx][ty + 8 * j];
        __nv_bfloat16 hi = __float2bfloat16(v);
        float r = v - __bfloat162float(hi);
        size_t o = ((size_t)b * SEQ + (l0 + ty + 8 * j)) * DIM + d0 + tx;
        g_xt_hi[o] = hi;
        g_xt_lo[o] = __float2bfloat16(r);
    }
}

// ---------------------------------------------------------------------------
// bf16 mma.sync GEMM with 3-term split (hi*hi + hi*lo + lo*hi), fp32 acc.
// hg[m = dir*512+e][n = l] per batch.  CTA tile 128x128, BK=64, 8 warps (2x4),
// warp tile 64x32 = 4x4 m16n8 fragments.  cp.async double-buffered stages.
// Smem tiles: 128 rows x 64 bf16, row stride 72 elems (144 B) -> ldmatrix
// bank pattern 4r mod 32, conflict-free.
// ---------------------------------------------------------------------------
#define ROWB      144                       // bytes per smem row (72 bf16)
#define TILE_B    (128 * ROWB)              // 18432 B per operand tile
#define OFF_AHI   0
#define OFF_ALO   (TILE_B)
#define OFF_BHI   (2 * TILE_B)
#define OFF_BLO   (3 * TILE_B)
#define STAGE_B   (4 * TILE_B)              // 73728 B
#define GEMM_SMEM (2 * STAGE_B)             // 147456 B

__global__ __launch_bounds__(256, 1)
void gemm_mma_kernel(const float* __restrict__ bias_fore, const float* __restrict__ bias_back)
{
    extern __shared__ __align__(16) char smraw[];
    const uint32_t sbase = smem_u32(smraw);

    const int tid  = threadIdx.x;
    const int lane = tid & 31;
    const int wid  = tid >> 5;
    const int wm   = wid >> 2;          // 0..1
    const int wn   = wid & 3;           // 0..3

    const int mt = blockIdx.x;          // 0..7  (global m rows mt*128..+127)
    const int nt = blockIdx.y;          // 0..63
    const int b  = blockIdx.z;          // batch
    const int m0 = mt * 128;
    const int n0 = nt * 128;

    const __nv_bfloat16* __restrict__ Whi = g_w_hi + (size_t)m0 * DIM;
    const __nv_bfloat16* __restrict__ Wlo = g_w_lo + (size_t)m0 * DIM;
    const __nv_bfloat16* __restrict__ Xhi = g_xt_hi + ((size_t)b * SEQ + n0) * DIM;
    const __nv_bfloat16* __restrict__ Xlo = g_xt_lo + ((size_t)b * SEQ + n0) * DIM;

    // Stage loader: 4 tiles of 128x64 bf16 = 1024 16B chunks each; 4 chunks/thread/tile.
    auto load_stage = [&](int s) {
        const int k0 = s * 64;
        const uint32_t buf = sbase + (s & 1) * STAGE_B;
#pragma unroll
        for (int it = 0; it < 4; it++) {
            int u   = tid + 256 * it;           // 0..1023
            int row = u >> 3, c = u & 7;
            uint32_t doff = (uint32_t)row * ROWB + c * 16;
            size_t   goff = (size_t)row * DIM + k0 + c * 8;
            cpasync16(buf + OFF_AHI + doff, Whi + goff);
            cpasync16(buf + OFF_ALO + doff, Wlo + goff);
            cpasync16(buf + OFF_BHI + doff, Xhi + goff);
            cpasync16(buf + OFF_BLO + doff, Xlo + goff);
        }
        CP_COMMIT();
    };

    float acc[4][4][4];
#pragma unroll
    for (int i = 0; i < 4; i++)
#pragma unroll
        for (int j = 0; j < 4; j++)
#pragma unroll
            for (int q = 0; q < 4; q++) acc[i][j][q] = 0.f;

    // Per-thread ldmatrix base byte offsets within a tile.
    // A: row = wm*64 + (lane&15) [+ mt4*16], col elems = (lane>>4)*8 [+ ks*16]
    const uint32_t a_base = (uint32_t)(wm * 64 + (lane & 15)) * ROWB + ((lane >> 4) * 8) * 2;
    // B: n-row = wn*32 + (lane&7) + ((lane&16)>>1) [+ np*16], col = (lane&8 ? 8 : 0) [+ ks*16]
    const uint32_t b_base = (uint32_t)(wn * 32 + (lane & 7) + ((lane & 16) >> 1)) * ROWB
                          + (uint32_t)(lane & 8) * 2;

    load_stage(0);

    for (int s = 0; s < 8; s++) {
        if (s < 7) {
            load_stage(s + 1);
            asm volatile("cp.async.wait_group 1;" ::: "memory");
        } else {
            asm volatile("cp.async.wait_group 0;" ::: "memory");
        }
        __syncthreads();

        const uint32_t buf = sbase + (s & 1) * STAGE_B;
#pragma unroll
        for (int ks = 0; ks < 4; ks++) {
            const uint32_t kb = ks * 32;                 // 16 elems * 2 B
            uint32_t ah[4][4], al[4][4], bh[2][4], bl[2][4];
#pragma unroll
            for (int m4 = 0; m4 < 4; m4++) {
                uint32_t ad = buf + a_base + (uint32_t)m4 * 16 * ROWB + kb;
                LDSM_X4(ah[m4][0], ah[m4][1], ah[m4][2], ah[m4][3], ad + OFF_AHI);
                LDSM_X4(al[m4][0], al[m4][1], al[m4][2], al[m4][3], ad + OFF_ALO);
            }
#pragma unroll
            for (int np = 0; np < 2; np++) {
                uint32_t bd = buf + b_base + (uint32_t)np * 16 * ROWB + kb;
                LDSM_X4(bh[np][0], bh[np][1], bh[np][2], bh[np][3], bd + OFF_BHI);
                LDSM_X4(bl[np][0], bl[np][1], bl[np][2], bl[np][3], bd + OFF_BLO);
            }
#pragma unroll
            for (int m4 = 0; m4 < 4; m4++)
#pragma unroll
                for (int n4 = 0; n4 < 4; n4++) {
                    const int np = n4 >> 1, h = (n4 & 1) * 2;
                    MMA16816(acc[m4][n4], ah[m4], bh[np][h], bh[np][h + 1]);   // hi*hi
                    MMA16816(acc[m4][n4], ah[m4], bl[np][h], bl[np][h + 1]);   // hi*lo
                    MMA16816(acc[m4][n4], al[m4], bh[np][h], bh[np][h + 1]);   // lo*hi
                }
        }
        __syncthreads();
    }

    // Epilogue: C fragment c0,c1 -> (m=gid, n=qp..qp+1), c2,c3 -> (m=gid+8).
    const int dirM = (m0 >= DIM) ? 1 : 0;
    const float* __restrict__ bias = dirM ? bias_back : bias_fore;
    const int gid = lane >> 2;
    const int qp  = (lane & 3) * 2;

#pragma unroll
    for (int m4 = 0; m4 < 4; m4++) {
#pragma unroll
        for (int hh = 0; hh < 2; hh++) {
            int m = m0 + wm * 64 + m4 * 16 + gid + hh * 8;
            int e = m & (DIM - 1);
            float bi = bias[e];
            float* __restrict__ C = g_hg + (((size_t)dirM * BATCH + b) * DIM + e) * SEQ
                                  + n0 + wn * 32 + qp;
#pragma unroll
            for (int n4 = 0; n4 < 4; n4++) {
                float2 v = make_float2(acc[m4][n4][hh * 2] + bi, acc[m4][n4][hh * 2 + 1] + bi);
                *reinterpret_cast<float2*>(C + n4 * 8) = v;
            }
        }
    }
}

// ---------------------------------------------------------------------------
// minGRU scan (unchanged from passing R10 kernel).
// h_t = a_t*h_{t-1} + b_t, a=sigmoid(-g), b=sigmoid(g)*g(h), h0=0.
// ---------------------------------------------------------------------------
#define IDX(p) ((p) + ((p) >> 5))
#define SCAN_SMEM_ELEMS (SEQ + (SEQ >> 5))

__global__ __launch_bounds__(256, 3)
void scan_kernel(const float* __restrict__ hg, float* __restrict__ out)
{
    extern __shared__ float smem[];
    float* sa = smem;
    float* sb = smem + SCAN_SMEM_ELEMS;

    __shared__ float wA[256];
    __shared__ float wB[256];

    const int id  = blockIdx.x;
    const int dir = id >> 11;
    const int rem = id & 2047;
    const int b   = rem >> 8;
    const int ch  = rem & 255;

    const float* __restrict__ hrow = hg + (((size_t)dir * BATCH + b) * DIM + ch) * SEQ;
    const float* __restrict__ grow = hrow + (size_t)HALF * SEQ;

    const int tid = threadIdx.x;

    for (int t = tid; t < SEQ; t += 256) {
        float h = hrow[t];
        float g = grow[t];
        float s = 1.f / (1.f + __expf(-g));
        float a = 1.f / (1.f + __expf(g));
        float gh = (h >= 0.f) ? (1.f + h) : __expf(h);
        int p = dir ? (SEQ - 1 - t) : t;
        sa[IDX(p)] = a;
        sb[IDX(p)] = s * gh;
    }
    __syncthreads();

    const int base = tid * 32;
    float A = 1.f, Bc = 0.f;
#pragma unroll
    for (int j = 0; j < 32; j++) {
        float at = sa[IDX(base + j)];
        float bt = sb[IDX(base + j)];
        A  = at * A;
        Bc = fmaf(at, Bc, bt);
    }
    wA[tid] = A;
    wB[tid] = Bc;
    __syncthreads();

    float ca = A, cb = Bc;
    for (int off = 1; off < 256; off <<= 1) {
        float pa = 1.f, pb = 0.f;
        if (tid >= off) { pa = wA[tid - off]; pb = wB[tid - off]; }
        __syncthreads();
        float na = ca * pa;
        float nb = fmaf(ca, pb, cb);
        ca = na; cb = nb;
        wA[tid] = ca;
        wB[tid] = cb;
        __syncthreads();
    }

    float h = (tid == 0) ? 0.f : wB[tid - 1];
#pragma unroll
    for (int j = 0; j < 32; j++) {
        float at = sa[IDX(base + j)];
        h = fmaf(at, h, sb[IDX(base + j)]);
        sb[IDX(base + j)] = h;
    }
    __syncthreads();

    float* __restrict__ orow = out + (((size_t)b * DIM) + dir * HALF + ch) * SEQ;
    for (int t = tid; t < SEQ; t += 256) {
        int l = dir ? (SEQ - 1 - t) : t;
        orow[l] = sb[IDX(t)];
    }
}

// ---------------------------------------------------------------------------
// Launch — stateless, graph-capturable
// ---------------------------------------------------------------------------
extern "C" void kernel_launch(void* const* d_in, const int* in_sizes, int n_in,
                              void* d_out, int out_size)
{
    const float* x      = (const float*)d_in[0];
    const float* w_fore = (const float*)d_in[1];
    const float* b_fore = (const float*)d_in[2];
    const float* w_back = (const float*)d_in[3];
    const float* b_back = (const float*)d_in[4];
    float* out = (float*)d_out;

    float* hg = nullptr;
    cudaGetSymbolAddress((void**)&hg, g_hg);

    // Prepass: bf16 hi/lo conversion (X transposed to [b][l][d]).
    wconv_kernel<<<2 * DIM * DIM / 256, 256>>>(w_fore, w_back);
    xconv_kernel<<<dim3(SEQ / 32, DIM / 32, BATCH), 256>>>(x);

    // Tensor-core GEMM (mma.sync bf16 3-term).  mt fastest -> B-tile L2 reuse x8.
    cudaFuncSetAttribute(gemm_mma_kernel, cudaFuncAttributeMaxDynamicSharedMemorySize, GEMM_SMEM);
    gemm_mma_kernel<<<dim3(8, 64, BATCH), 256, GEMM_SMEM>>>(b_fore, b_back);

    // Scan.
    const size_t smem_bytes = 2 * SCAN_SMEM_ELEMS * sizeof(float);
    cudaFuncSetAttribute(scan_kernel, cudaFuncAttributeMaxDynamicSharedMemorySize, (int)smem_bytes);
    scan_kernel<<<2 * BATCH * HALF, 256, smem_bytes>>>(hg, out);
}